// round 13
// baseline (speedup 1.0000x reference)
#include <cuda_runtime.h>
#include <cuda_bf16.h>
#include <cstdint>

#define SEQ  2048
#define WORD 1024
#define EMB  128
#define NH   16
#define NSPLIT 8
#define HK   (NH * EMB)            /* 2048 */
#define QSC  0.1275174405080890f   /* (1/sqrt(128)) * log2(e) */

typedef unsigned long long u64;

// ---------------- device scratch (no allocations allowed) ----------------
__device__ float g_Pp[NSPLIT * SEQ * EMB];    // proj split-K partials

__device__ __align__(16) __nv_bfloat16 g_xhi[SEQ * WORD];
__device__ __align__(16) __nv_bfloat16 g_xlo[SEQ * WORD];
__device__ __align__(16) __nv_bfloat16 g_Whi[48 * WORD * EMB];   // [z][w][e]
__device__ __align__(16) __nv_bfloat16 g_Wlo[48 * WORD * EMB];
__device__ __align__(16) __nv_bfloat16 g_Qhi[NH * SEQ * EMB];    // scaled by QSC
__device__ __align__(16) __nv_bfloat16 g_Qlo[NH * SEQ * EMB];
__device__ __align__(16) __nv_bfloat16 g_Khi[NH * SEQ * EMB];
__device__ __align__(16) __nv_bfloat16 g_Klo[NH * SEQ * EMB];
__device__ __align__(16) __nv_bfloat16 g_Vhi[NH * SEQ * EMB];
__device__ __align__(16) __nv_bfloat16 g_Vlo[NH * SEQ * EMB];
__device__ __align__(16) __nv_bfloat16 g_Zhi[SEQ * HK];          // [s][h*EMB+e]
__device__ __align__(16) __nv_bfloat16 g_Zlo[SEQ * HK];
__device__ __align__(16) __nv_bfloat16 g_Phi[HK * EMB];          // proj split
__device__ __align__(16) __nv_bfloat16 g_Plo[HK * EMB];

// ---------------- helpers ----------------
__device__ __forceinline__ float ex2f_(float x) {
    float y; asm("ex2.approx.ftz.f32 %0, %1;" : "=f"(y) : "f"(x)); return y;
}
__device__ __forceinline__ void mma16816(float* c, const uint32_t* a, uint32_t b0, uint32_t b1) {
    asm volatile(
        "mma.sync.aligned.m16n8k16.row.col.f32.bf16.bf16.f32 "
        "{%0,%1,%2,%3}, {%4,%5,%6,%7}, {%8,%9}, {%0,%1,%2,%3};"
        : "+f"(c[0]), "+f"(c[1]), "+f"(c[2]), "+f"(c[3])
        : "r"(a[0]), "r"(a[1]), "r"(a[2]), "r"(a[3]), "r"(b0), "r"(b1));
}
#define LDSM4(R, addr) \
    asm volatile("ldmatrix.sync.aligned.m8n8.x4.shared.b16 {%0,%1,%2,%3}, [%4];" \
        : "=r"((R)[0]), "=r"((R)[1]), "=r"((R)[2]), "=r"((R)[3]) : "r"(addr))
#define LDSM4T(R, addr) \
    asm volatile("ldmatrix.sync.aligned.m8n8.x4.trans.shared.b16 {%0,%1,%2,%3}, [%4];" \
        : "=r"((R)[0]), "=r"((R)[1]), "=r"((R)[2]), "=r"((R)[3]) : "r"(addr))
__device__ __forceinline__ void cpa(uint32_t dst, const void* src) {
    asm volatile("cp.async.cg.shared.global [%0], [%1], 16;" :: "r"(dst), "l"(src));
}
#define CP_COMMIT() asm volatile("cp.async.commit_group;")
__device__ __forceinline__ uint32_t smem_u32(const void* p) {
    uint32_t a;
    asm("{ .reg .u64 t; cvta.to.shared.u64 t, %1; cvt.u32.u64 %0, t; }" : "=r"(a) : "l"(p));
    return a;
}
__device__ __forceinline__ uint32_t pk(__nv_bfloat16 a, __nv_bfloat16 b) {
    uint16_t ua = *(uint16_t*)&a, ub = *(uint16_t*)&b;
    return (uint32_t)ua | ((uint32_t)ub << 16);
}
__device__ __forceinline__ void split_bf(float v, __nv_bfloat16& hi, __nv_bfloat16& lo) {
    hi = __float2bfloat16(v);
    lo = __float2bfloat16(v - __bfloat162float(hi));
}

// =======================================================================
// conv kernels: fp32 -> bf16 hi/lo splits
// =======================================================================
__global__ __launch_bounds__(256)
void conv_x(const float* __restrict__ x)
{
    int i = (blockIdx.x * 256 + threadIdx.x) * 4;
    float4 v = *(const float4*)&x[i];
    __nv_bfloat16 h0, h1, h2, h3, l0, l1, l2, l3;
    split_bf(v.x, h0, l0); split_bf(v.y, h1, l1);
    split_bf(v.z, h2, l2); split_bf(v.w, h3, l3);
    *(uint2*)&g_xhi[i] = make_uint2(pk(h0, h1), pk(h2, h3));
    *(uint2*)&g_xlo[i] = make_uint2(pk(l0, l1), pk(l2, l3));
}

__global__ __launch_bounds__(256)
void conv_w(const float* __restrict__ Wq, const float* __restrict__ Wk,
            const float* __restrict__ Wv)
{
    const int WE = WORD * EMB;
    int i = (blockIdx.x * 256 + threadIdx.x) * 4;
    int z = i / WE;
    int off = i - z * WE;
    const float* W = (z < 16 ? Wq : (z < 32 ? Wk : Wv));
    int hh = (z < 16 ? z : (z < 32 ? z - 16 : z - 32));
    float4 v = *(const float4*)&W[hh * WE + off];
    __nv_bfloat16 h0, h1, h2, h3, l0, l1, l2, l3;
    split_bf(v.x, h0, l0); split_bf(v.y, h1, l1);
    split_bf(v.z, h2, l2); split_bf(v.w, h3, l3);
    *(uint2*)&g_Whi[i] = make_uint2(pk(h0, h1), pk(h2, h3));
    *(uint2*)&g_Wlo[i] = make_uint2(pk(l0, l1), pk(l2, l3));
}

__global__ __launch_bounds__(256)
void conv_p(const float* __restrict__ proj)
{
    int i = (blockIdx.x * 256 + threadIdx.x) * 4;
    float4 v = *(const float4*)&proj[i];
    __nv_bfloat16 h0, h1, h2, h3, l0, l1, l2, l3;
    split_bf(v.x, h0, l0); split_bf(v.y, h1, l1);
    split_bf(v.z, h2, l2); split_bf(v.w, h3, l3);
    *(uint2*)&g_Phi[i] = make_uint2(pk(h0, h1), pk(h2, h3));
    *(uint2*)&g_Plo[i] = make_uint2(pk(l0, l1), pk(l2, l3));
}

// =======================================================================
// gemm_qkv_mma (R11 best config): 3-term bf16 split HMMA GEMM.
//   256 threads, 4x2 warp grid, 3-stage cp.async ring.
//   wait_group fixed on final chunk (was a latent race).
// =======================================================================
#define XT_SZ  18432                 /* 128 x 72 bf16 (144B rows) */
#define WT_SZ  17408                 /* 64 x 136 bf16 (272B rows) */
#define QKV_BUF (2*XT_SZ + 2*WT_SZ)  /* 71680 */
#define QKV_SMEM3 (3*QKV_BUF)        /* 215040 */
#define PRJ_SMEM  (2*QKV_BUF)        /* 143360 */

__global__ __launch_bounds__(256, 1)
void gemm_qkv_mma(const float* __restrict__ bq, const float* __restrict__ bk,
                  const float* __restrict__ bv)
{
    extern __shared__ char smem[];
    const uint32_t sb = smem_u32(smem);
    const int tid = threadIdx.x, w = tid >> 5, lane = tid & 31;
    const int z = blockIdx.y, kind = z >> 4, h = z & 15;
    const int row0 = blockIdx.x * 128;
    const float* bp = (kind == 0 ? bq : (kind == 1 ? bk : bv)) + h * EMB;
    const int wr = w >> 1, wc = w & 1;          // 4 row-groups x 2 col-groups

    const __nv_bfloat16* xh = g_xhi + (size_t)row0 * WORD;
    const __nv_bfloat16* xl = g_xlo + (size_t)row0 * WORD;
    const __nv_bfloat16* wh = g_Whi + (size_t)z * WORD * EMB;
    const __nv_bfloat16* wl = g_Wlo + (size_t)z * WORD * EMB;

    auto issue = [&](int kt) {
        uint32_t b = sb + (kt % 3) * QKV_BUF;
        int k0 = kt * 64;
#pragma unroll
        for (int t = 0; t < 4; t++) {                  // x tiles [128][64]
            int idx = tid + t * 256;
            int r = idx >> 3, s = idx & 7;
            uint32_t d = b + r * 144 + s * 16;
            cpa(d,         xh + r * WORD + k0 + s * 8);
            cpa(d + XT_SZ, xl + r * WORD + k0 + s * 8);
        }
#pragma unroll
        for (int t = 0; t < 4; t++) {                  // W tiles [64][128]
            int idx = tid + t * 256;
            int r = idx >> 4, s = idx & 15;
            uint32_t d = b + 2 * XT_SZ + r * 272 + s * 16;
            cpa(d,         wh + (k0 + r) * EMB + s * 8);
            cpa(d + WT_SZ, wl + (k0 + r) * EMB + s * 8);
        }
        CP_COMMIT();
    };
    issue(0); issue(1);

    float c[2][8][4];
#pragma unroll
    for (int rt = 0; rt < 2; rt++)
#pragma unroll
        for (int j = 0; j < 8; j++)
#pragma unroll
            for (int p = 0; p < 4; p++) c[rt][j][p] = 0.f;

    const int g = lane >> 2, t4 = lane & 3;
    const uint32_t a_off = (uint32_t)((wr * 32 + (lane & 15)) * 144 + (lane >> 4) * 16);
    const uint32_t b_off = (uint32_t)(2 * XT_SZ +
        (((lane >> 3) & 1) * 8 + (lane & 7)) * 272 + wc * 128 + (lane >> 4) * 16);

#pragma unroll 1
    for (int kt = 0; kt < 16; kt++) {
        if (kt < 15) asm volatile("cp.async.wait_group 1;");
        else         asm volatile("cp.async.wait_group 0;");
        __syncthreads();                           // buf (kt+2)%3 free
        if (kt + 2 < 16) issue(kt + 2);
        const uint32_t xb = sb + (kt % 3) * QKV_BUF;

#pragma unroll
        for (int kk = 0; kk < 4; kk++) {
            uint32_t ah[2][4], al[2][4];
#pragma unroll
            for (int rt = 0; rt < 2; rt++) {
                uint32_t aa = xb + a_off + rt * 16 * 144 + kk * 32;
                LDSM4(ah[rt], aa);
                LDSM4(al[rt], aa + XT_SZ);
            }
#pragma unroll
            for (int np = 0; np < 4; np++) {
                uint32_t ba = xb + b_off + kk * 16 * 272 + np * 32;
                uint32_t bh[4], bl[4];
                LDSM4T(bh, ba);
                LDSM4T(bl, ba + WT_SZ);
#pragma unroll
                for (int rt = 0; rt < 2; rt++) {
                    mma16816(c[rt][2 * np],     ah[rt], bh[0], bh[1]);
                    mma16816(c[rt][2 * np],     al[rt], bh[0], bh[1]);
                    mma16816(c[rt][2 * np],     ah[rt], bl[0], bl[1]);
                    mma16816(c[rt][2 * np + 1], ah[rt], bh[2], bh[3]);
                    mma16816(c[rt][2 * np + 1], al[rt], bh[2], bh[3]);
                    mma16816(c[rt][2 * np + 1], ah[rt], bl[2], bl[3]);
                }
            }
        }
    }

    // ---- epilogue: bias, optional scale, split to bf16 hi/lo ----
    __nv_bfloat16 *dhi, *dlo;
    if (kind == 0)      { dhi = g_Qhi; dlo = g_Qlo; }
    else if (kind == 1) { dhi = g_Khi; dlo = g_Klo; }
    else                { dhi = g_Vhi; dlo = g_Vlo; }
    dhi += (size_t)h * SEQ * EMB;
    dlo += (size_t)h * SEQ * EMB;
    const float sc = (kind == 0) ? QSC : 1.0f;

#pragma unroll
    for (int rt = 0; rt < 2; rt++) {
        const int r0 = row0 + wr * 32 + rt * 16 + g, r1 = r0 + 8;
#pragma unroll
        for (int j = 0; j < 8; j++) {
            int col = wc * 64 + 8 * j + 2 * t4;
            float b0 = __ldg(&bp[col]), b1 = __ldg(&bp[col + 1]);
            float v00 = (c[rt][j][0] + b0) * sc, v01 = (c[rt][j][1] + b1) * sc;
            float v10 = (c[rt][j][2] + b0) * sc, v11 = (c[rt][j][3] + b1) * sc;
            __nv_bfloat16 h00, h01, h10, h11, l00, l01, l10, l11;
            split_bf(v00, h00, l00); split_bf(v01, h01, l01);
            split_bf(v10, h10, l10); split_bf(v11, h11, l11);
            *(uint32_t*)&dhi[r0 * EMB + col] = pk(h00, h01);
            *(uint32_t*)&dlo[r0 * EMB + col] = pk(l00, l01);
            *(uint32_t*)&dhi[r1 * EMB + col] = pk(h10, h11);
            *(uint32_t*)&dlo[r1 * EMB + col] = pk(l10, l11);
        }
    }
}

// =======================================================================
// attn_mma v3: FA2 flash attention, DEFERRED-PV pipeline.
//   At iter t: S_t mmas then PV_{t-1} mmas back-to-back (P_{t-1} stashed
//   in registers), softmax_t afterwards overlaps the tensor-pipe drain
//   and the next chunk's DMA. 3-stage KV ring (Q region = buffer 2).
// =======================================================================
#define QT_SZ  34816                  /* 128 x 136 bf16 */
#define KT_SZ  17408                  /* 64 x 136 bf16 */
#define AT_BUF (4*KT_SZ)              /* 69632 = 2*QT_SZ */
#define ATT_SMEM (3*AT_BUF)           /* 208896 */

__global__ __launch_bounds__(256, 1)
void attn_mma()
{
    extern __shared__ char smem[];
    const uint32_t sb = smem_u32(smem);
    const int tid = threadIdx.x, w = tid >> 5, lane = tid & 31;
    const int qb = blockIdx.x * 128, h = blockIdx.y;

    const __nv_bfloat16* Qh = g_Qhi + (size_t)h * SEQ * EMB + (size_t)qb * EMB;
    const __nv_bfloat16* Ql = g_Qlo + (size_t)h * SEQ * EMB + (size_t)qb * EMB;
    const __nv_bfloat16* Kh = g_Khi + (size_t)h * SEQ * EMB;
    const __nv_bfloat16* Kl = g_Klo + (size_t)h * SEQ * EMB;
    const __nv_bfloat16* Vh = g_Vhi + (size_t)h * SEQ * EMB;
    const __nv_bfloat16* Vl = g_Vlo + (size_t)h * SEQ * EMB;

    // Q -> ring buffer 2 region (temporarily)
    const uint32_t qbase = sb + 2 * AT_BUF;
#pragma unroll
    for (int t = 0; t < 8; t++) {
        int idx = tid + t * 256;
        int r = idx >> 4, s = idx & 15;
        uint32_t d = qbase + r * 272 + s * 16;
        cpa(d,         Qh + r * EMB + s * 8);
        cpa(d + QT_SZ, Ql + r * EMB + s * 8);
    }
    CP_COMMIT();

    auto issue = [&](int kt) {
        uint32_t b = sb + (kt % 3) * AT_BUF;
        int kb = kt * 64;
#pragma unroll
        for (int t = 0; t < 4; t++) {
            int idx = tid + t * 256;
            int r = idx >> 4, s = idx & 15;
            uint32_t d = b + r * 272 + s * 16;
            const int go = (kb + r) * EMB + s * 8;
            cpa(d,             Kh + go);
            cpa(d + KT_SZ,     Kl + go);
            cpa(d + 2 * KT_SZ, Vh + go);
            cpa(d + 3 * KT_SZ, Vl + go);
        }
        CP_COMMIT();
    };
    issue(0); issue(1);

    asm volatile("cp.async.wait_group 2;");   // Q arrived
    __syncthreads();

    uint32_t qah[8][4], qal[8][4];
    const uint32_t qa_off = (uint32_t)((w * 16 + (lane & 15)) * 272 + (lane >> 4) * 16);
#pragma unroll
    for (int kk = 0; kk < 8; kk++) {
        uint32_t a = qbase + qa_off + kk * 32;
        LDSM4(qah[kk], a);
        LDSM4(qal[kk], a + QT_SZ);
    }
    __syncthreads();                           // Q region now dead -> buffer 2

    float o[16][4];
#pragma unroll
    for (int j = 0; j < 16; j++)
#pragma unroll
        for (int p = 0; p < 4; p++) o[j][p] = 0.f;
    float mrow0 = -1e30f, mrow1 = -1e30f, lrow0 = 0.f, lrow1 = 0.f;

    uint32_t pah_s[4][4], pal_s[4][4];         // stashed P fragments (prev chunk)

    const int g = lane >> 2, t4 = lane & 3;
    const uint32_t kb_row = (uint32_t)(((lane >> 4) << 3) + (lane & 7));
    const uint32_t kb_cadd = (uint32_t)(((lane >> 3) & 1) * 16);
    const uint32_t vb_row = (uint32_t)((((lane >> 3) & 1) * 8) + (lane & 7));
    const uint32_t vb_cadd = (uint32_t)((lane >> 4) * 16);

#pragma unroll 1
    for (int kt = 0; kt < 32; kt++) {
        if (kt < 31) asm volatile("cp.async.wait_group 1;");
        else         asm volatile("cp.async.wait_group 0;");
        __syncthreads();                       // chunk kt visible
        const uint32_t kbuf = sb + (kt % 3) * AT_BUF;
        const uint32_t vbuf_prev = sb + ((kt + 2) % 3) * AT_BUF + 2 * KT_SZ; // (kt-1)%3

        // ---- S_t = Q @ K_t^T  (96 mmas) ----
        float s[8][4];
#pragma unroll
        for (int j = 0; j < 8; j++)
#pragma unroll
            for (int p = 0; p < 4; p++) s[j][p] = 0.f;
#pragma unroll
        for (int kk = 0; kk < 8; kk++) {
#pragma unroll
            for (int np = 0; np < 4; np++) {
                uint32_t ba = kbuf + (np * 16 + kb_row) * 272 + kk * 32 + kb_cadd;
                uint32_t bh[4], bl[4];
                LDSM4(bh, ba);
                LDSM4(bl, ba + KT_SZ);
                mma16816(s[2 * np],     qah[kk], bh[0], bh[1]);
                mma16816(s[2 * np],     qal[kk], bh[0], bh[1]);
                mma16816(s[2 * np],     qah[kk], bl[0], bl[1]);
                mma16816(s[2 * np + 1], qah[kk], bh[2], bh[3]);
                mma16816(s[2 * np + 1], qal[kk], bh[2], bh[3]);
                mma16816(s[2 * np + 1], qah[kk], bl[2], bl[3]);
            }
        }

        // ---- O += P_{t-1} @ V_{t-1}  (96 mmas, overlaps S_t drain) ----
        if (kt > 0) {
#pragma unroll
            for (int kk = 0; kk < 4; kk++) {
#pragma unroll
                for (int np = 0; np < 8; np++) {
                    uint32_t va = vbuf_prev + (kk * 16 + vb_row) * 272 + np * 32 + vb_cadd;
                    uint32_t vh4[4], vl4[4];
                    LDSM4T(vh4, va);
                    LDSM4T(vl4, va + KT_SZ);
                    mma16816(o[2 * np],     pah_s[kk], vh4[0], vh4[1]);
                    mma16816(o[2 * np],     pal_s[kk], vh4[0], vh4[1]);
                    mma16816(o[2 * np],     pah_s[kk], vl4[0], vl4[1]);
                    mma16816(o[2 * np + 1], pah_s[kk], vh4[2], vh4[3]);
                    mma16816(o[2 * np + 1], pal_s[kk], vh4[2], vh4[3]);
                    mma16816(o[2 * np + 1], pah_s[kk], vl4[2], vl4[3]);
                }
            }
        }
        __syncthreads();                       // buf (kt-1) reads done
        if (kt + 2 < 32) issue(kt + 2);        // overwrites buf (kt-1)%3

        // ---- softmax_t (scalar; overlaps DMA + pipe drain) ----
        float mx0 = -1e30f, mx1 = -1e30f;
#pragma unroll
        for (int j = 0; j < 8; j++) {
            mx0 = fmaxf(mx0, fmaxf(s[j][0], s[j][1]));
            mx1 = fmaxf(mx1, fmaxf(s[j][2], s[j][3]));
        }
        mx0 = fmaxf(mx0, __shfl_xor_sync(0xffffffffu, mx0, 1));
        mx0 = fmaxf(mx0, __shfl_xor_sync(0xffffffffu, mx0, 2));
        mx1 = fmaxf(mx1, __shfl_xor_sync(0xffffffffu, mx1, 1));
        mx1 = fmaxf(mx1, __shfl_xor_sync(0xffffffffu, mx1, 2));
        float mn0 = fmaxf(mrow0, mx0), mn1 = fmaxf(mrow1, mx1);
        float al0 = ex2f_(mrow0 - mn0), al1 = ex2f_(mrow1 - mn1);
        float rs0 = 0.f, rs1 = 0.f;
#pragma unroll
        for (int j = 0; j < 8; j++) {
            s[j][0] = ex2f_(s[j][0] - mn0);
            s[j][1] = ex2f_(s[j][1] - mn0);
            s[j][2] = ex2f_(s[j][2] - mn1);
            s[j][3] = ex2f_(s[j][3] - mn1);
            rs0 += s[j][0] + s[j][1];
            rs1 += s[j][2] + s[j][3];
        }
        rs0 += __shfl_xor_sync(0xffffffffu, rs0, 1);
        rs0 += __shfl_xor_sync(0xffffffffu, rs0, 2);
        rs1 += __shfl_xor_sync(0xffffffffu, rs1, 1);
        rs1 += __shfl_xor_sync(0xffffffffu, rs1, 2);
        lrow0 = lrow0 * al0 + rs0; mrow0 = mn0;
        lrow1 = lrow1 * al1 + rs1; mrow1 = mn1;
#pragma unroll
        for (int j = 0; j < 16; j++) {
            o[j][0] *= al0; o[j][1] *= al0; o[j][2] *= al1; o[j][3] *= al1;
        }

        // ---- stash P_t fragments for next iteration's PV ----
#pragma unroll
        for (int kk = 0; kk < 4; kk++) {
            __nv_bfloat16 ph[8], pl[8];
            split_bf(s[2 * kk][0], ph[0], pl[0]);
            split_bf(s[2 * kk][1], ph[1], pl[1]);
            split_bf(s[2 * kk][2], ph[2], pl[2]);
            split_bf(s[2 * kk][3], ph[3], pl[3]);
            split_bf(s[2 * kk + 1][0], ph[4], pl[4]);
            split_bf(s[2 * kk + 1][1], ph[5], pl[5]);
            split_bf(s[2 * kk + 1][2], ph[6], pl[6]);
            split_bf(s[2 * kk + 1][3], ph[7], pl[7]);
            pah_s[kk][0] = pk(ph[0], ph[1]); pah_s[kk][1] = pk(ph[2], ph[3]);
            pah_s[kk][2] = pk(ph[4], ph[5]); pah_s[kk][3] = pk(ph[6], ph[7]);
            pal_s[kk][0] = pk(pl[0], pl[1]); pal_s[kk][1] = pk(pl[2], pl[3]);
            pal_s[kk][2] = pk(pl[4], pl[5]); pal_s[kk][3] = pk(pl[6], pl[7]);
        }
    }

    // ---- flush PV_31 (buf 31%3 = 2... = (31%3)) ----
    {
        const uint32_t vbuf_last = sb + (31 % 3) * AT_BUF + 2 * KT_SZ;
#pragma unroll
        for (int kk = 0; kk < 4; kk++) {
#pragma unroll
            for (int np = 0; np < 8; np++) {
                uint32_t va = vbuf_last + (kk * 16 + vb_row) * 272 + np * 32 + vb_cadd;
                uint32_t vh4[4], vl4[4];
                LDSM4T(vh4, va);
                LDSM4T(vl4, va + KT_SZ);
                mma16816(o[2 * np],     pah_s[kk], vh4[0], vh4[1]);
                mma16816(o[2 * np],     pal_s[kk], vh4[0], vh4[1]);
                mma16816(o[2 * np],     pah_s[kk], vl4[0], vl4[1]);
                mma16816(o[2 * np + 1], pah_s[kk], vh4[2], vh4[3]);
                mma16816(o[2 * np + 1], pal_s[kk], vh4[2], vh4[3]);
                mma16816(o[2 * np + 1], pah_s[kk], vl4[2], vl4[3]);
            }
        }
    }

    // ---- epilogue: normalize, split to bf16 hi/lo into g_Zhi/g_Zlo ----
    const float rl0 = 1.0f / lrow0, rl1 = 1.0f / lrow1;
    const int r0 = qb + w * 16 + g, r1 = r0 + 8;
    __nv_bfloat16* Zh0 = g_Zhi + (size_t)r0 * HK + h * EMB;
    __nv_bfloat16* Zl0 = g_Zlo + (size_t)r0 * HK + h * EMB;
    __nv_bfloat16* Zh1 = g_Zhi + (size_t)r1 * HK + h * EMB;
    __nv_bfloat16* Zl1 = g_Zlo + (size_t)r1 * HK + h * EMB;
#pragma unroll
    for (int j = 0; j < 16; j++) {
        int col = 8 * j + 2 * t4;
        float v00 = o[j][0] * rl0, v01 = o[j][1] * rl0;
        float v10 = o[j][2] * rl1, v11 = o[j][3] * rl1;
        __nv_bfloat16 h00, h01, h10, h11, l00, l01, l10, l11;
        split_bf(v00, h00, l00); split_bf(v01, h01, l01);
        split_bf(v10, h10, l10); split_bf(v11, h11, l11);
        *(uint32_t*)&Zh0[col] = pk(h00, h01);
        *(uint32_t*)&Zl0[col] = pk(l00, l01);
        *(uint32_t*)&Zh1[col] = pk(h10, h11);
        *(uint32_t*)&Zl1[col] = pk(l10, l11);
    }
}

// =======================================================================
// gemm_proj_mma: split-K proj on HMMA (2-stage, unchanged).
// =======================================================================
__global__ __launch_bounds__(256, 1)
void gemm_proj_mma()
{
    extern __shared__ char smem[];
    const uint32_t sb = smem_u32(smem);
    const int tid = threadIdx.x, w = tid >> 5, lane = tid & 31;
    const int row0 = blockIdx.x * 128;
    const int ks   = blockIdx.y;
    const int wr = w >> 1, wc = w & 1;

    const __nv_bfloat16* zh = g_Zhi + (size_t)row0 * HK + ks * 256;
    const __nv_bfloat16* zl = g_Zlo + (size_t)row0 * HK + ks * 256;
    const __nv_bfloat16* ph = g_Phi + (size_t)ks * 256 * EMB;
    const __nv_bfloat16* pl = g_Plo + (size_t)ks * 256 * EMB;

    auto issue = [&](int kt) {
        uint32_t b = sb + (kt & 1) * QKV_BUF;
        int k0 = kt * 64;
#pragma unroll
        for (int t = 0; t < 4; t++) {
            int idx = tid + t * 256;
            int r = idx >> 3, s = idx & 7;
            uint32_t d = b + r * 144 + s * 16;
            cpa(d,         zh + r * HK + k0 + s * 8);
            cpa(d + XT_SZ, zl + r * HK + k0 + s * 8);
        }
#pragma unroll
        for (int t = 0; t < 4; t++) {
            int idx = tid + t * 256;
            int r = idx >> 4, s = idx & 15;
            uint32_t d = b + 2 * XT_SZ + r * 272 + s * 16;
            cpa(d,         ph + (k0 + r) * EMB + s * 8);
            cpa(d + WT_SZ, pl + (k0 + r) * EMB + s * 8);
        }
        CP_COMMIT();
    };
    issue(0); issue(1);

    float c[2][8][4];
#pragma unroll
    for (int rt = 0; rt < 2; rt++)
#pragma unroll
        for (int j = 0; j < 8; j++)
#pragma unroll
            for (int p = 0; p < 4; p++) c[rt][j][p] = 0.f;

    const int g = lane >> 2, t4 = lane & 3;
    const uint32_t a_off = (uint32_t)((wr * 32 + (lane & 15)) * 144 + (lane >> 4) * 16);
    const uint32_t b_off = (uint32_t)(2 * XT_SZ +
        (((lane >> 3) & 1) * 8 + (lane & 7)) * 272 + wc * 128 + (lane >> 4) * 16);

#pragma unroll 1
    for (int kt = 0; kt < 4; kt++) {
        if (kt < 3) asm volatile("cp.async.wait_group 1;");
        else        asm volatile("cp.async.wait_group 0;");
        __syncthreads();
        const uint32_t xb = sb + (kt & 1) * QKV_BUF;

#pragma unroll
        for (int kk = 0; kk < 4; kk++) {
            uint32_t ah[2][4], al[2][4];
#pragma unroll
            for (int rt = 0; rt < 2; rt++) {
                uint32_t aa = xb + a_off + rt * 16 * 144 + kk * 32;
                LDSM4(ah[rt], aa);
                LDSM4(al[rt], aa + XT_SZ);
            }
#pragma unroll
            for (int np = 0; np < 4; np++) {
                uint32_t ba = xb + b_off + kk * 16 * 272 + np * 32;
                uint32_t bh[4], bl[4];
                LDSM4T(bh, ba);
                LDSM4T(bl, ba + WT_SZ);
#pragma unroll
                for (int rt = 0; rt < 2; rt++) {
                    mma16816(c[rt][2 * np],     ah[rt], bh[0], bh[1]);
                    mma16816(c[rt][2 * np],     al[rt], bh[0], bh[1]);
                    mma16816(c[rt][2 * np],     ah[rt], bl[0], bl[1]);
                    mma16816(c[rt][2 * np + 1], ah[rt], bh[2], bh[3]);
                    mma16816(c[rt][2 * np + 1], al[rt], bh[2], bh[3]);
                    mma16816(c[rt][2 * np + 1], ah[rt], bl[2], bl[3]);
                }
            }
        }
        __syncthreads();
        if (kt + 2 < 4) issue(kt + 2);
    }

    float* Pp = g_Pp + (size_t)blockIdx.y * SEQ * EMB;
#pragma unroll
    for (int rt = 0; rt < 2; rt++) {
        const int r0 = row0 + wr * 32 + rt * 16 + g, r1 = r0 + 8;
#pragma unroll
        for (int j = 0; j < 8; j++) {
            int col = wc * 64 + 8 * j + 2 * t4;
            *(float2*)&Pp[r0 * EMB + col] = make_float2(c[rt][j][0], c[rt][j][1]);
            *(float2*)&Pp[r1 * EMB + col] = make_float2(c[rt][j][2], c[rt][j][3]);
        }
    }
}

__global__ __launch_bounds__(256)
void proj_reduce(float* __restrict__ out)
{
    int gid = blockIdx.x * 256 + threadIdx.x;
    const float4* p = (const float4*)g_Pp;
    const int STR = SEQ * EMB / 4;
    float4 s = p[gid];
#pragma unroll
    for (int z = 1; z < NSPLIT; z++) {
        float4 t = p[z * STR + gid];
        s.x += t.x; s.y += t.y; s.z += t.z; s.w += t.w;
    }
    ((float4*)out)[gid] = s;
}

// =======================================================================
extern "C" void kernel_launch(void* const* d_in, const int* in_sizes, int n_in,
                              void* d_out, int out_size)
{
    (void)in_sizes; (void)n_in; (void)out_size;
    const float* x    = (const float*)d_in[0];
    const float* Wq   = (const float*)d_in[1];
    const float* bq   = (const float*)d_in[2];
    const float* Wk   = (const float*)d_in[3];
    const float* bk   = (const float*)d_in[4];
    const float* Wv   = (const float*)d_in[5];
    const float* bv   = (const float*)d_in[6];
    const float* proj = (const float*)d_in[7];
    float* out = (float*)d_out;

    cudaFuncSetAttribute(gemm_qkv_mma,  cudaFuncAttributeMaxDynamicSharedMemorySize, QKV_SMEM3);
    cudaFuncSetAttribute(attn_mma,      cudaFuncAttributeMaxDynamicSharedMemorySize, ATT_SMEM);
    cudaFuncSetAttribute(gemm_proj_mma, cudaFuncAttributeMaxDynamicSharedMemorySize, PRJ_SMEM);

    conv_x<<<SEQ * WORD / 1024, 256>>>(x);
    conv_w<<<48 * WORD * EMB / 1024, 256>>>(Wq, Wk, Wv);
    conv_p<<<HK * EMB / 1024, 256>>>(proj);

    gemm_qkv_mma<<<dim3(SEQ / 128, 48), 256, QKV_SMEM3>>>(bq, bk, bv);

    attn_mma<<<dim3(SEQ / 128, NH), 256, ATT_SMEM>>>();

    gemm_proj_mma<<<dim3(SEQ / 128, NSPLIT), 256, PRJ_SMEM>>>();
    proj_reduce<<<SEQ * EMB / 1024, 256>>>(out);
}

// round 14
// speedup vs baseline: 1.4604x; 1.4604x over previous
#include <cuda_runtime.h>
#include <cuda_fp16.h>
#include <cstdint>

#define SEQ  2048
#define WORD 1024
#define EMB  128
#define NH   16
#define NSPLIT 8
#define HK   (NH * EMB)            /* 2048 */
#define QSC  0.1275174405080890f   /* (1/sqrt(128)) * log2(e) */

typedef unsigned long long u64;

// ---------------- device scratch (no allocations allowed) ----------------
__device__ float g_Pp[NSPLIT * SEQ * EMB];    // proj split-K partials

// A-side operands: fp16 hi+lo pairs. B-side operands: single fp16.
__device__ __align__(16) __half g_xhi[SEQ * WORD];
__device__ __align__(16) __half g_xlo[SEQ * WORD];
__device__ __align__(16) __half g_W  [48 * WORD * EMB];   // [z][w][e] single
__device__ __align__(16) __half g_Qhi[NH * SEQ * EMB];    // scaled by QSC
__device__ __align__(16) __half g_Qlo[NH * SEQ * EMB];
__device__ __align__(16) __half g_K  [NH * SEQ * EMB];    // single
__device__ __align__(16) __half g_V  [NH * SEQ * EMB];    // single
__device__ __align__(16) __half g_Zhi[SEQ * HK];          // [s][h*EMB+e]
__device__ __align__(16) __half g_Zlo[SEQ * HK];
__device__ __align__(16) __half g_P  [HK * EMB];          // proj single

// ---------------- helpers ----------------
__device__ __forceinline__ float ex2f_(float x) {
    float y; asm("ex2.approx.ftz.f32 %0, %1;" : "=f"(y) : "f"(x)); return y;
}
__device__ __forceinline__ void mma16816(float* c, const uint32_t* a, uint32_t b0, uint32_t b1) {
    asm volatile(
        "mma.sync.aligned.m16n8k16.row.col.f32.f16.f16.f32 "
        "{%0,%1,%2,%3}, {%4,%5,%6,%7}, {%8,%9}, {%0,%1,%2,%3};"
        : "+f"(c[0]), "+f"(c[1]), "+f"(c[2]), "+f"(c[3])
        : "r"(a[0]), "r"(a[1]), "r"(a[2]), "r"(a[3]), "r"(b0), "r"(b1));
}
#define LDSM4(R, addr) \
    asm volatile("ldmatrix.sync.aligned.m8n8.x4.shared.b16 {%0,%1,%2,%3}, [%4];" \
        : "=r"((R)[0]), "=r"((R)[1]), "=r"((R)[2]), "=r"((R)[3]) : "r"(addr))
#define LDSM4T(R, addr) \
    asm volatile("ldmatrix.sync.aligned.m8n8.x4.trans.shared.b16 {%0,%1,%2,%3}, [%4];" \
        : "=r"((R)[0]), "=r"((R)[1]), "=r"((R)[2]), "=r"((R)[3]) : "r"(addr))
__device__ __forceinline__ void cpa(uint32_t dst, const void* src) {
    asm volatile("cp.async.cg.shared.global [%0], [%1], 16;" :: "r"(dst), "l"(src));
}
#define CP_COMMIT() asm volatile("cp.async.commit_group;")
__device__ __forceinline__ uint32_t smem_u32(const void* p) {
    uint32_t a;
    asm("{ .reg .u64 t; cvta.to.shared.u64 t, %1; cvt.u32.u64 %0, t; }" : "=r"(a) : "l"(p));
    return a;
}
__device__ __forceinline__ uint32_t pkh(__half a, __half b) {
    uint16_t ua = *(uint16_t*)&a, ub = *(uint16_t*)&b;
    return (uint32_t)ua | ((uint32_t)ub << 16);
}
__device__ __forceinline__ void split_h(float v, __half& hi, __half& lo) {
    hi = __float2half_rn(v);
    lo = __float2half_rn(v - __half2float(hi));
}

// =======================================================================
// conv kernels
// =======================================================================
__global__ __launch_bounds__(256)
void conv_x(const float* __restrict__ x)
{
    int i = (blockIdx.x * 256 + threadIdx.x) * 4;
    float4 v = *(const float4*)&x[i];
    __half h0, h1, h2, h3, l0, l1, l2, l3;
    split_h(v.x, h0, l0); split_h(v.y, h1, l1);
    split_h(v.z, h2, l2); split_h(v.w, h3, l3);
    *(uint2*)&g_xhi[i] = make_uint2(pkh(h0, h1), pkh(h2, h3));
    *(uint2*)&g_xlo[i] = make_uint2(pkh(l0, l1), pkh(l2, l3));
}

__global__ __launch_bounds__(256)
void conv_w(const float* __restrict__ Wq, const float* __restrict__ Wk,
            const float* __restrict__ Wv)
{
    const int WE = WORD * EMB;
    int i = (blockIdx.x * 256 + threadIdx.x) * 4;
    int z = i / WE;
    int off = i - z * WE;
    const float* W = (z < 16 ? Wq : (z < 32 ? Wk : Wv));
    int hh = (z < 16 ? z : (z < 32 ? z - 16 : z - 32));
    float4 v = *(const float4*)&W[hh * WE + off];
    *(uint2*)&g_W[i] = make_uint2(pkh(__float2half_rn(v.x), __float2half_rn(v.y)),
                                  pkh(__float2half_rn(v.z), __float2half_rn(v.w)));
}

__global__ __launch_bounds__(256)
void conv_p(const float* __restrict__ proj)
{
    int i = (blockIdx.x * 256 + threadIdx.x) * 4;
    float4 v = *(const float4*)&proj[i];
    *(uint2*)&g_P[i] = make_uint2(pkh(__float2half_rn(v.x), __float2half_rn(v.y)),
                                  pkh(__float2half_rn(v.z), __float2half_rn(v.w)));
}

// =======================================================================
// gemm_qkv_mma: fp16 2-term split HMMA GEMM (A hi+lo, B single).
//   256 threads, 4x2 warp grid, 3-stage cp.async ring.
// =======================================================================
#define XT_SZ  18432                 /* 128 x 72 fp16 (144B rows) */
#define WT_SZ  17408                 /* 64 x 136 fp16 (272B rows) */
#define QKV_BUF (2*XT_SZ + WT_SZ)    /* 54272 */
#define QKV_SMEM3 (3*QKV_BUF)        /* 162816 */
#define PRJ_SMEM  (2*QKV_BUF)        /* 108544 */

__global__ __launch_bounds__(256, 1)
void gemm_qkv_mma(const float* __restrict__ bq, const float* __restrict__ bk,
                  const float* __restrict__ bv)
{
    extern __shared__ char smem[];
    const uint32_t sb = smem_u32(smem);
    const int tid = threadIdx.x, w = tid >> 5, lane = tid & 31;
    const int z = blockIdx.y, kind = z >> 4, h = z & 15;
    const int row0 = blockIdx.x * 128;
    const float* bp = (kind == 0 ? bq : (kind == 1 ? bk : bv)) + h * EMB;
    const int wr = w >> 1, wc = w & 1;          // 4 row-groups x 2 col-groups

    const __half* xh = g_xhi + (size_t)row0 * WORD;
    const __half* xl = g_xlo + (size_t)row0 * WORD;
    const __half* wp = g_W   + (size_t)z * WORD * EMB;

    auto issue = [&](int kt) {
        uint32_t b = sb + (kt % 3) * QKV_BUF;
        int k0 = kt * 64;
#pragma unroll
        for (int t = 0; t < 4; t++) {                  // x tiles [128][64] hi+lo
            int idx = tid + t * 256;
            int r = idx >> 3, s = idx & 7;
            uint32_t d = b + r * 144 + s * 16;
            cpa(d,         xh + r * WORD + k0 + s * 8);
            cpa(d + XT_SZ, xl + r * WORD + k0 + s * 8);
        }
#pragma unroll
        for (int t = 0; t < 4; t++) {                  // W tile [64][128] single
            int idx = tid + t * 256;
            int r = idx >> 4, s = idx & 15;
            cpa(b + 2 * XT_SZ + r * 272 + s * 16, wp + (k0 + r) * EMB + s * 8);
        }
        CP_COMMIT();
    };
    issue(0); issue(1);

    float c[2][8][4];
#pragma unroll
    for (int rt = 0; rt < 2; rt++)
#pragma unroll
        for (int j = 0; j < 8; j++)
#pragma unroll
            for (int p = 0; p < 4; p++) c[rt][j][p] = 0.f;

    const int g = lane >> 2, t4 = lane & 3;
    const uint32_t a_off = (uint32_t)((wr * 32 + (lane & 15)) * 144 + (lane >> 4) * 16);
    const uint32_t b_off = (uint32_t)(2 * XT_SZ +
        (((lane >> 3) & 1) * 8 + (lane & 7)) * 272 + wc * 128 + (lane >> 4) * 16);

#pragma unroll 1
    for (int kt = 0; kt < 16; kt++) {
        if (kt < 15) asm volatile("cp.async.wait_group 1;");
        else         asm volatile("cp.async.wait_group 0;");
        __syncthreads();                           // buf (kt+2)%3 free
        if (kt + 2 < 16) issue(kt + 2);
        const uint32_t xb = sb + (kt % 3) * QKV_BUF;

#pragma unroll
        for (int kk = 0; kk < 4; kk++) {
            uint32_t ah[2][4], al[2][4];
#pragma unroll
            for (int rt = 0; rt < 2; rt++) {
                uint32_t aa = xb + a_off + rt * 16 * 144 + kk * 32;
                LDSM4(ah[rt], aa);
                LDSM4(al[rt], aa + XT_SZ);
            }
#pragma unroll
            for (int np = 0; np < 4; np++) {
                uint32_t ba = xb + b_off + kk * 16 * 272 + np * 32;
                uint32_t bh[4];
                LDSM4T(bh, ba);
#pragma unroll
                for (int rt = 0; rt < 2; rt++) {
                    mma16816(c[rt][2 * np],     ah[rt], bh[0], bh[1]);
                    mma16816(c[rt][2 * np],     al[rt], bh[0], bh[1]);
                    mma16816(c[rt][2 * np + 1], ah[rt], bh[2], bh[3]);
                    mma16816(c[rt][2 * np + 1], al[rt], bh[2], bh[3]);
                }
            }
        }
    }

    // ---- epilogue: bias; Q -> scaled hi/lo, K/V -> single fp16 ----
    const float sc = (kind == 0) ? QSC : 1.0f;
#pragma unroll
    for (int rt = 0; rt < 2; rt++) {
        const int r0 = row0 + wr * 32 + rt * 16 + g, r1 = r0 + 8;
#pragma unroll
        for (int j = 0; j < 8; j++) {
            int col = wc * 64 + 8 * j + 2 * t4;
            float b0 = __ldg(&bp[col]), b1 = __ldg(&bp[col + 1]);
            float v00 = (c[rt][j][0] + b0) * sc, v01 = (c[rt][j][1] + b1) * sc;
            float v10 = (c[rt][j][2] + b0) * sc, v11 = (c[rt][j][3] + b1) * sc;
            if (kind == 0) {
                __half h00, h01, h10, h11, l00, l01, l10, l11;
                split_h(v00, h00, l00); split_h(v01, h01, l01);
                split_h(v10, h10, l10); split_h(v11, h11, l11);
                __half* dh = g_Qhi + (size_t)h * SEQ * EMB;
                __half* dl = g_Qlo + (size_t)h * SEQ * EMB;
                *(uint32_t*)&dh[r0 * EMB + col] = pkh(h00, h01);
                *(uint32_t*)&dl[r0 * EMB + col] = pkh(l00, l01);
                *(uint32_t*)&dh[r1 * EMB + col] = pkh(h10, h11);
                *(uint32_t*)&dl[r1 * EMB + col] = pkh(l10, l11);
            } else {
                __half* dd = (kind == 1 ? g_K : g_V) + (size_t)h * SEQ * EMB;
                *(uint32_t*)&dd[r0 * EMB + col] = pkh(__float2half_rn(v00), __float2half_rn(v01));
                *(uint32_t*)&dd[r1 * EMB + col] = pkh(__float2half_rn(v10), __float2half_rn(v11));
            }
        }
    }
}

// =======================================================================
// attn_mma: FA2 flash attention, fp16 2-term (Q/P hi+lo, K/V single).
//   Q resident in its own smem region; 3-stage K|V ring.
// =======================================================================
#define QT_SZ  34816                  /* 128 x 136 fp16 */
#define KT_SZ  17408                  /* 64 x 136 fp16 */
#define AT_BUF (2*KT_SZ)              /* 34816: K | V */
#define ATT_SMEM (3*AT_BUF + 2*QT_SZ) /* 174080 */

__global__ __launch_bounds__(256, 1)
void attn_mma()
{
    extern __shared__ char smem[];
    const uint32_t sb = smem_u32(smem);
    const int tid = threadIdx.x, w = tid >> 5, lane = tid & 31;
    const int qb = blockIdx.x * 128, h = blockIdx.y;

    const __half* Qh = g_Qhi + (size_t)h * SEQ * EMB + (size_t)qb * EMB;
    const __half* Ql = g_Qlo + (size_t)h * SEQ * EMB + (size_t)qb * EMB;
    const __half* Kp = g_K   + (size_t)h * SEQ * EMB;
    const __half* Vp = g_V   + (size_t)h * SEQ * EMB;

    const uint32_t qbase = sb + 3 * AT_BUF;
#pragma unroll
    for (int t = 0; t < 8; t++) {
        int idx = tid + t * 256;
        int r = idx >> 4, s = idx & 15;
        uint32_t d = qbase + r * 272 + s * 16;
        cpa(d,         Qh + r * EMB + s * 8);
        cpa(d + QT_SZ, Ql + r * EMB + s * 8);
    }
    CP_COMMIT();

    auto issue = [&](int kt) {
        uint32_t b = sb + (kt % 3) * AT_BUF;
        int kb = kt * 64;
#pragma unroll
        for (int t = 0; t < 4; t++) {
            int idx = tid + t * 256;
            int r = idx >> 4, s = idx & 15;
            uint32_t d = b + r * 272 + s * 16;
            const int go = (kb + r) * EMB + s * 8;
            cpa(d,         Kp + go);
            cpa(d + KT_SZ, Vp + go);
        }
        CP_COMMIT();
    };
    issue(0); issue(1);

    asm volatile("cp.async.wait_group 2;");   // Q arrived
    __syncthreads();

    uint32_t qah[8][4], qal[8][4];
    const uint32_t qa_off = (uint32_t)((w * 16 + (lane & 15)) * 272 + (lane >> 4) * 16);
#pragma unroll
    for (int kk = 0; kk < 8; kk++) {
        uint32_t a = qbase + qa_off + kk * 32;
        LDSM4(qah[kk], a);
        LDSM4(qal[kk], a + QT_SZ);
    }

    float o[16][4];
#pragma unroll
    for (int j = 0; j < 16; j++)
#pragma unroll
        for (int p = 0; p < 4; p++) o[j][p] = 0.f;
    float mrow0 = -1e30f, mrow1 = -1e30f, lrow0 = 0.f, lrow1 = 0.f;

    const int g = lane >> 2, t4 = lane & 3;
    const uint32_t kb_row = (uint32_t)(((lane >> 4) << 3) + (lane & 7));
    const uint32_t kb_cadd = (uint32_t)(((lane >> 3) & 1) * 16);
    const uint32_t vb_row = (uint32_t)((((lane >> 3) & 1) * 8) + (lane & 7));
    const uint32_t vb_cadd = (uint32_t)((lane >> 4) * 16);

#pragma unroll 1
    for (int kt = 0; kt < 32; kt++) {
        if (kt < 31) asm volatile("cp.async.wait_group 1;");
        else         asm volatile("cp.async.wait_group 0;");
        __syncthreads();
        if (kt + 2 < 32) issue(kt + 2);
        const uint32_t kbuf = sb + (kt % 3) * AT_BUF;

        // ---- S = Q @ K^T  (2-term, 128 mmas) ----
        float s[8][4];
#pragma unroll
        for (int j = 0; j < 8; j++)
#pragma unroll
            for (int p = 0; p < 4; p++) s[j][p] = 0.f;
#pragma unroll
        for (int kk = 0; kk < 8; kk++) {
#pragma unroll
            for (int np = 0; np < 4; np++) {
                uint32_t ba = kbuf + (np * 16 + kb_row) * 272 + kk * 32 + kb_cadd;
                uint32_t bh[4];
                LDSM4(bh, ba);
                mma16816(s[2 * np],     qah[kk], bh[0], bh[1]);
                mma16816(s[2 * np],     qal[kk], bh[0], bh[1]);
                mma16816(s[2 * np + 1], qah[kk], bh[2], bh[3]);
                mma16816(s[2 * np + 1], qal[kk], bh[2], bh[3]);
            }
        }

        // ---- online softmax ----
        float mx0 = -1e30f, mx1 = -1e30f;
#pragma unroll
        for (int j = 0; j < 8; j++) {
            mx0 = fmaxf(mx0, fmaxf(s[j][0], s[j][1]));
            mx1 = fmaxf(mx1, fmaxf(s[j][2], s[j][3]));
        }
        mx0 = fmaxf(mx0, __shfl_xor_sync(0xffffffffu, mx0, 1));
        mx0 = fmaxf(mx0, __shfl_xor_sync(0xffffffffu, mx0, 2));
        mx1 = fmaxf(mx1, __shfl_xor_sync(0xffffffffu, mx1, 1));
        mx1 = fmaxf(mx1, __shfl_xor_sync(0xffffffffu, mx1, 2));
        float mn0 = fmaxf(mrow0, mx0), mn1 = fmaxf(mrow1, mx1);
        float al0 = ex2f_(mrow0 - mn0), al1 = ex2f_(mrow1 - mn1);
        float rs0 = 0.f, rs1 = 0.f;
#pragma unroll
        for (int j = 0; j < 8; j++) {
            s[j][0] = ex2f_(s[j][0] - mn0);
            s[j][1] = ex2f_(s[j][1] - mn0);
            s[j][2] = ex2f_(s[j][2] - mn1);
            s[j][3] = ex2f_(s[j][3] - mn1);
            rs0 += s[j][0] + s[j][1];
            rs1 += s[j][2] + s[j][3];
        }
        rs0 += __shfl_xor_sync(0xffffffffu, rs0, 1);
        rs0 += __shfl_xor_sync(0xffffffffu, rs0, 2);
        rs1 += __shfl_xor_sync(0xffffffffu, rs1, 1);
        rs1 += __shfl_xor_sync(0xffffffffu, rs1, 2);
        lrow0 = lrow0 * al0 + rs0; mrow0 = mn0;
        lrow1 = lrow1 * al1 + rs1; mrow1 = mn1;
#pragma unroll
        for (int j = 0; j < 16; j++) {
            o[j][0] *= al0; o[j][1] *= al0; o[j][2] *= al1; o[j][3] *= al1;
        }

        // ---- O += P @ V  (P hi+lo, V single; 128 mmas) ----
        const uint32_t vbuf = kbuf + KT_SZ;
#pragma unroll
        for (int kk = 0; kk < 4; kk++) {
            uint32_t pah[4], pal[4];
            {
                __half ph[8], pl[8];
                split_h(s[2 * kk][0], ph[0], pl[0]);
                split_h(s[2 * kk][1], ph[1], pl[1]);
                split_h(s[2 * kk][2], ph[2], pl[2]);
                split_h(s[2 * kk][3], ph[3], pl[3]);
                split_h(s[2 * kk + 1][0], ph[4], pl[4]);
                split_h(s[2 * kk + 1][1], ph[5], pl[5]);
                split_h(s[2 * kk + 1][2], ph[6], pl[6]);
                split_h(s[2 * kk + 1][3], ph[7], pl[7]);
                pah[0] = pkh(ph[0], ph[1]); pah[1] = pkh(ph[2], ph[3]);
                pah[2] = pkh(ph[4], ph[5]); pah[3] = pkh(ph[6], ph[7]);
                pal[0] = pkh(pl[0], pl[1]); pal[1] = pkh(pl[2], pl[3]);
                pal[2] = pkh(pl[4], pl[5]); pal[3] = pkh(pl[6], pl[7]);
            }
#pragma unroll
            for (int np = 0; np < 8; np++) {
                uint32_t va = vbuf + (kk * 16 + vb_row) * 272 + np * 32 + vb_cadd;
                uint32_t vh4[4];
                LDSM4T(vh4, va);
                mma16816(o[2 * np],     pah, vh4[0], vh4[1]);
                mma16816(o[2 * np],     pal, vh4[0], vh4[1]);
                mma16816(o[2 * np + 1], pah, vh4[2], vh4[3]);
                mma16816(o[2 * np + 1], pal, vh4[2], vh4[3]);
            }
        }
    }

    // ---- epilogue: normalize, split to fp16 hi/lo into g_Zhi/g_Zlo ----
    const float rl0 = 1.0f / lrow0, rl1 = 1.0f / lrow1;
    const int r0 = qb + w * 16 + g, r1 = r0 + 8;
    __half* Zh0 = g_Zhi + (size_t)r0 * HK + h * EMB;
    __half* Zl0 = g_Zlo + (size_t)r0 * HK + h * EMB;
    __half* Zh1 = g_Zhi + (size_t)r1 * HK + h * EMB;
    __half* Zl1 = g_Zlo + (size_t)r1 * HK + h * EMB;
#pragma unroll
    for (int j = 0; j < 16; j++) {
        int col = 8 * j + 2 * t4;
        float v00 = o[j][0] * rl0, v01 = o[j][1] * rl0;
        float v10 = o[j][2] * rl1, v11 = o[j][3] * rl1;
        __half h00, h01, h10, h11, l00, l01, l10, l11;
        split_h(v00, h00, l00); split_h(v01, h01, l01);
        split_h(v10, h10, l10); split_h(v11, h11, l11);
        *(uint32_t*)&Zh0[col] = pkh(h00, h01);
        *(uint32_t*)&Zl0[col] = pkh(l00, l01);
        *(uint32_t*)&Zh1[col] = pkh(h10, h11);
        *(uint32_t*)&Zl1[col] = pkh(l10, l11);
    }
}

// =======================================================================
// gemm_proj_mma: split-K proj (Z hi+lo, proj single), 2-stage.
// =======================================================================
__global__ __launch_bounds__(256, 1)
void gemm_proj_mma()
{
    extern __shared__ char smem[];
    const uint32_t sb = smem_u32(smem);
    const int tid = threadIdx.x, w = tid >> 5, lane = tid & 31;
    const int row0 = blockIdx.x * 128;
    const int ks   = blockIdx.y;
    const int wr = w >> 1, wc = w & 1;

    const __half* zh = g_Zhi + (size_t)row0 * HK + ks * 256;
    const __half* zl = g_Zlo + (size_t)row0 * HK + ks * 256;
    const __half* pp = g_P   + (size_t)ks * 256 * EMB;

    auto issue = [&](int kt) {
        uint32_t b = sb + (kt & 1) * QKV_BUF;
        int k0 = kt * 64;
#pragma unroll
        for (int t = 0; t < 4; t++) {
            int idx = tid + t * 256;
            int r = idx >> 3, s = idx & 7;
            uint32_t d = b + r * 144 + s * 16;
            cpa(d,         zh + r * HK + k0 + s * 8);
            cpa(d + XT_SZ, zl + r * HK + k0 + s * 8);
        }
#pragma unroll
        for (int t = 0; t < 4; t++) {
            int idx = tid + t * 256;
            int r = idx >> 4, s = idx & 15;
            cpa(b + 2 * XT_SZ + r * 272 + s * 16, pp + (k0 + r) * EMB + s * 8);
        }
        CP_COMMIT();
    };
    issue(0); issue(1);

    float c[2][8][4];
#pragma unroll
    for (int rt = 0; rt < 2; rt++)
#pragma unroll
        for (int j = 0; j < 8; j++)
#pragma unroll
            for (int p = 0; p < 4; p++) c[rt][j][p] = 0.f;

    const int g = lane >> 2, t4 = lane & 3;
    const uint32_t a_off = (uint32_t)((wr * 32 + (lane & 15)) * 144 + (lane >> 4) * 16);
    const uint32_t b_off = (uint32_t)(2 * XT_SZ +
        (((lane >> 3) & 1) * 8 + (lane & 7)) * 272 + wc * 128 + (lane >> 4) * 16);

#pragma unroll 1
    for (int kt = 0; kt < 4; kt++) {
        if (kt < 3) asm volatile("cp.async.wait_group 1;");
        else        asm volatile("cp.async.wait_group 0;");
        __syncthreads();
        const uint32_t xb = sb + (kt & 1) * QKV_BUF;

#pragma unroll
        for (int kk = 0; kk < 4; kk++) {
            uint32_t ah[2][4], al[2][4];
#pragma unroll
            for (int rt = 0; rt < 2; rt++) {
                uint32_t aa = xb + a_off + rt * 16 * 144 + kk * 32;
                LDSM4(ah[rt], aa);
                LDSM4(al[rt], aa + XT_SZ);
            }
#pragma unroll
            for (int np = 0; np < 4; np++) {
                uint32_t ba = xb + b_off + kk * 16 * 272 + np * 32;
                uint32_t bh[4];
                LDSM4T(bh, ba);
#pragma unroll
                for (int rt = 0; rt < 2; rt++) {
                    mma16816(c[rt][2 * np],     ah[rt], bh[0], bh[1]);
                    mma16816(c[rt][2 * np],     al[rt], bh[0], bh[1]);
                    mma16816(c[rt][2 * np + 1], ah[rt], bh[2], bh[3]);
                    mma16816(c[rt][2 * np + 1], al[rt], bh[2], bh[3]);
                }
            }
        }
        __syncthreads();
        if (kt + 2 < 4) issue(kt + 2);
    }

    float* Pp = g_Pp + (size_t)blockIdx.y * SEQ * EMB;
#pragma unroll
    for (int rt = 0; rt < 2; rt++) {
        const int r0 = row0 + wr * 32 + rt * 16 + g, r1 = r0 + 8;
#pragma unroll
        for (int j = 0; j < 8; j++) {
            int col = wc * 64 + 8 * j + 2 * t4;
            *(float2*)&Pp[r0 * EMB + col] = make_float2(c[rt][j][0], c[rt][j][1]);
            *(float2*)&Pp[r1 * EMB + col] = make_float2(c[rt][j][2], c[rt][j][3]);
        }
    }
}

__global__ __launch_bounds__(256)
void proj_reduce(float* __restrict__ out)
{
    int gid = blockIdx.x * 256 + threadIdx.x;
    const float4* p = (const float4*)g_Pp;
    const int STR = SEQ * EMB / 4;
    float4 s = p[gid];
#pragma unroll
    for (int z = 1; z < NSPLIT; z++) {
        float4 t = p[z * STR + gid];
        s.x += t.x; s.y += t.y; s.z += t.z; s.w += t.w;
    }
    ((float4*)out)[gid] = s;
}

// =======================================================================
extern "C" void kernel_launch(void* const* d_in, const int* in_sizes, int n_in,
                              void* d_out, int out_size)
{
    (void)in_sizes; (void)n_in; (void)out_size;
    const float* x    = (const float*)d_in[0];
    const float* Wq   = (const float*)d_in[1];
    const float* bq   = (const float*)d_in[2];
    const float* Wk   = (const float*)d_in[3];
    const float* bk   = (const float*)d_in[4];
    const float* Wv   = (const float*)d_in[5];
    const float* bv   = (const float*)d_in[6];
    const float* proj = (const float*)d_in[7];
    float* out = (float*)d_out;

    cudaFuncSetAttribute(gemm_qkv_mma,  cudaFuncAttributeMaxDynamicSharedMemorySize, QKV_SMEM3);
    cudaFuncSetAttribute(attn_mma,      cudaFuncAttributeMaxDynamicSharedMemorySize, ATT_SMEM);
    cudaFuncSetAttribute(gemm_proj_mma, cudaFuncAttributeMaxDynamicSharedMemorySize, PRJ_SMEM);

    conv_x<<<SEQ * WORD / 1024, 256>>>(x);
    conv_w<<<48 * WORD * EMB / 1024, 256>>>(Wq, Wk, Wv);
    conv_p<<<HK * EMB / 1024, 256>>>(proj);

    gemm_qkv_mma<<<dim3(SEQ / 128, 48), 256, QKV_SMEM3>>>(bq, bk, bv);

    attn_mma<<<dim3(SEQ / 128, NH), 256, ATT_SMEM>>>();

    gemm_proj_mma<<<dim3(SEQ / 128, NSPLIT), 256, PRJ_SMEM>>>();
    proj_reduce<<<SEQ * EMB / 1024, 256>>>(out);
}

// round 15
// speedup vs baseline: 2.5042x; 1.7148x over previous
#include <cuda_runtime.h>
#include <cuda_fp16.h>
#include <cstdint>

#define SEQ  2048
#define WORD 1024
#define EMB  128
#define NH   16
#define NSPLIT 8
#define HK   (NH * EMB)            /* 2048 */
#define QSC  0.1275174405080890f   /* (1/sqrt(128)) * log2(e) */

// ---------------- device scratch (no allocations allowed) ----------------
__device__ float g_Pp[NSPLIT * SEQ * EMB];    // proj split-K partials

// all operands single fp16 (1-term scheme)
__device__ __align__(16) __half g_x  [SEQ * WORD];
__device__ __align__(16) __half g_W  [48 * WORD * EMB];   // [z][w][e]
__device__ __align__(16) __half g_Q  [NH * SEQ * EMB];    // scaled by QSC
__device__ __align__(16) __half g_K  [NH * SEQ * EMB];
__device__ __align__(16) __half g_V  [NH * SEQ * EMB];
__device__ __align__(16) __half g_Z  [SEQ * HK];          // [s][h*EMB+e]
__device__ __align__(16) __half g_P  [HK * EMB];          // proj

// ---------------- helpers ----------------
__device__ __forceinline__ float ex2f_(float x) {
    float y; asm("ex2.approx.ftz.f32 %0, %1;" : "=f"(y) : "f"(x)); return y;
}
__device__ __forceinline__ void mma16816(float* c, const uint32_t* a, uint32_t b0, uint32_t b1) {
    asm volatile(
        "mma.sync.aligned.m16n8k16.row.col.f32.f16.f16.f32 "
        "{%0,%1,%2,%3}, {%4,%5,%6,%7}, {%8,%9}, {%0,%1,%2,%3};"
        : "+f"(c[0]), "+f"(c[1]), "+f"(c[2]), "+f"(c[3])
        : "r"(a[0]), "r"(a[1]), "r"(a[2]), "r"(a[3]), "r"(b0), "r"(b1));
}
#define LDSM4(R, addr) \
    asm volatile("ldmatrix.sync.aligned.m8n8.x4.shared.b16 {%0,%1,%2,%3}, [%4];" \
        : "=r"((R)[0]), "=r"((R)[1]), "=r"((R)[2]), "=r"((R)[3]) : "r"(addr))
#define LDSM4T(R, addr) \
    asm volatile("ldmatrix.sync.aligned.m8n8.x4.trans.shared.b16 {%0,%1,%2,%3}, [%4];" \
        : "=r"((R)[0]), "=r"((R)[1]), "=r"((R)[2]), "=r"((R)[3]) : "r"(addr))
__device__ __forceinline__ void cpa(uint32_t dst, const void* src) {
    asm volatile("cp.async.cg.shared.global [%0], [%1], 16;" :: "r"(dst), "l"(src));
}
#define CP_COMMIT() asm volatile("cp.async.commit_group;")
__device__ __forceinline__ uint32_t smem_u32(const void* p) {
    uint32_t a;
    asm("{ .reg .u64 t; cvta.to.shared.u64 t, %1; cvt.u32.u64 %0, t; }" : "=r"(a) : "l"(p));
    return a;
}
__device__ __forceinline__ uint32_t pkh(__half a, __half b) {
    uint16_t ua = *(uint16_t*)&a, ub = *(uint16_t*)&b;
    return (uint32_t)ua | ((uint32_t)ub << 16);
}

// =======================================================================
// conv kernels: fp32 -> single fp16
// =======================================================================
__global__ __launch_bounds__(256)
void conv_x(const float* __restrict__ x)
{
    int i = (blockIdx.x * 256 + threadIdx.x) * 4;
    float4 v = *(const float4*)&x[i];
    *(uint2*)&g_x[i] = make_uint2(pkh(__float2half_rn(v.x), __float2half_rn(v.y)),
                                  pkh(__float2half_rn(v.z), __float2half_rn(v.w)));
}

__global__ __launch_bounds__(256)
void conv_w(const float* __restrict__ Wq, const float* __restrict__ Wk,
            const float* __restrict__ Wv)
{
    const int WE = WORD * EMB;
    int i = (blockIdx.x * 256 + threadIdx.x) * 4;
    int z = i / WE;
    int off = i - z * WE;
    const float* W = (z < 16 ? Wq : (z < 32 ? Wk : Wv));
    int hh = (z < 16 ? z : (z < 32 ? z - 16 : z - 32));
    float4 v = *(const float4*)&W[hh * WE + off];
    *(uint2*)&g_W[i] = make_uint2(pkh(__float2half_rn(v.x), __float2half_rn(v.y)),
                                  pkh(__float2half_rn(v.z), __float2half_rn(v.w)));
}

__global__ __launch_bounds__(256)
void conv_p(const float* __restrict__ proj)
{
    int i = (blockIdx.x * 256 + threadIdx.x) * 4;
    float4 v = *(const float4*)&proj[i];
    *(uint2*)&g_P[i] = make_uint2(pkh(__float2half_rn(v.x), __float2half_rn(v.y)),
                                  pkh(__float2half_rn(v.z), __float2half_rn(v.w)));
}

// =======================================================================
// gemm_qkv_mma: 1-term fp16 HMMA GEMM.
//   256 threads, 4x2 warp grid, 3-stage cp.async ring. 105 KB smem ->
//   2 CTAs/SM possible.
// =======================================================================
#define XT_SZ  18432                 /* 128 x 72 fp16 (144B rows) */
#define WT_SZ  17408                 /* 64 x 136 fp16 (272B rows) */
#define QKV_BUF (XT_SZ + WT_SZ)      /* 35840 */
#define QKV_SMEM3 (3*QKV_BUF)        /* 107520 */
#define PRJ_SMEM  (2*QKV_BUF)        /* 71680 */

__global__ __launch_bounds__(256, 2)
void gemm_qkv_mma(const float* __restrict__ bq, const float* __restrict__ bk,
                  const float* __restrict__ bv)
{
    extern __shared__ char smem[];
    const uint32_t sb = smem_u32(smem);
    const int tid = threadIdx.x, w = tid >> 5, lane = tid & 31;
    const int z = blockIdx.y, kind = z >> 4, h = z & 15;
    const int row0 = blockIdx.x * 128;
    const float* bp = (kind == 0 ? bq : (kind == 1 ? bk : bv)) + h * EMB;
    const int wr = w >> 1, wc = w & 1;          // 4 row-groups x 2 col-groups

    const __half* xp = g_x + (size_t)row0 * WORD;
    const __half* wp = g_W + (size_t)z * WORD * EMB;

    auto issue = [&](int kt) {
        uint32_t b = sb + (kt % 3) * QKV_BUF;
        int k0 = kt * 64;
#pragma unroll
        for (int t = 0; t < 4; t++) {                  // x tile [128][64]
            int idx = tid + t * 256;
            int r = idx >> 3, s = idx & 7;
            cpa(b + r * 144 + s * 16, xp + r * WORD + k0 + s * 8);
        }
#pragma unroll
        for (int t = 0; t < 4; t++) {                  // W tile [64][128]
            int idx = tid + t * 256;
            int r = idx >> 4, s = idx & 15;
            cpa(b + XT_SZ + r * 272 + s * 16, wp + (k0 + r) * EMB + s * 8);
        }
        CP_COMMIT();
    };
    issue(0); issue(1);

    float c[2][8][4];
#pragma unroll
    for (int rt = 0; rt < 2; rt++)
#pragma unroll
        for (int j = 0; j < 8; j++)
#pragma unroll
            for (int p = 0; p < 4; p++) c[rt][j][p] = 0.f;

    const int g = lane >> 2, t4 = lane & 3;
    const uint32_t a_off = (uint32_t)((wr * 32 + (lane & 15)) * 144 + (lane >> 4) * 16);
    const uint32_t b_off = (uint32_t)(XT_SZ +
        (((lane >> 3) & 1) * 8 + (lane & 7)) * 272 + wc * 128 + (lane >> 4) * 16);

#pragma unroll 1
    for (int kt = 0; kt < 16; kt++) {
        if (kt < 15) asm volatile("cp.async.wait_group 1;");
        else         asm volatile("cp.async.wait_group 0;");
        __syncthreads();                           // buf (kt+2)%3 free
        if (kt + 2 < 16) issue(kt + 2);
        const uint32_t xb = sb + (kt % 3) * QKV_BUF;

#pragma unroll
        for (int kk = 0; kk < 4; kk++) {
            uint32_t ah[2][4];
#pragma unroll
            for (int rt = 0; rt < 2; rt++)
                LDSM4(ah[rt], xb + a_off + rt * 16 * 144 + kk * 32);
#pragma unroll
            for (int np = 0; np < 4; np++) {
                uint32_t ba = xb + b_off + kk * 16 * 272 + np * 32;
                uint32_t bh[4];
                LDSM4T(bh, ba);
#pragma unroll
                for (int rt = 0; rt < 2; rt++) {
                    mma16816(c[rt][2 * np],     ah[rt], bh[0], bh[1]);
                    mma16816(c[rt][2 * np + 1], ah[rt], bh[2], bh[3]);
                }
            }
        }
    }

    // ---- epilogue: bias; Q scaled; all -> single fp16 ----
    const float sc = (kind == 0) ? QSC : 1.0f;
    __half* dd = (kind == 0 ? g_Q : (kind == 1 ? g_K : g_V)) + (size_t)h * SEQ * EMB;
#pragma unroll
    for (int rt = 0; rt < 2; rt++) {
        const int r0 = row0 + wr * 32 + rt * 16 + g, r1 = r0 + 8;
#pragma unroll
        for (int j = 0; j < 8; j++) {
            int col = wc * 64 + 8 * j + 2 * t4;
            float b0 = __ldg(&bp[col]), b1 = __ldg(&bp[col + 1]);
            float v00 = (c[rt][j][0] + b0) * sc, v01 = (c[rt][j][1] + b1) * sc;
            float v10 = (c[rt][j][2] + b0) * sc, v11 = (c[rt][j][3] + b1) * sc;
            *(uint32_t*)&dd[r0 * EMB + col] = pkh(__float2half_rn(v00), __float2half_rn(v01));
            *(uint32_t*)&dd[r1 * EMB + col] = pkh(__float2half_rn(v10), __float2half_rn(v11));
        }
    }
}

// =======================================================================
// attn_mma: FA2 flash attention, 1-term fp16.
//   Q resident (34 KB), 3-stage K|V ring (104 KB). 139 KB total.
// =======================================================================
#define KT_SZ  17408                  /* 64 x 136 fp16 */
#define AT_BUF (2*KT_SZ)              /* 34816: K | V */
#define QT_SZ  34816                  /* 128 x 136 fp16 */
#define ATT_SMEM (3*AT_BUF + QT_SZ)   /* 139264 */

__global__ __launch_bounds__(256, 1)
void attn_mma()
{
    extern __shared__ char smem[];
    const uint32_t sb = smem_u32(smem);
    const int tid = threadIdx.x, w = tid >> 5, lane = tid & 31;
    const int qb = blockIdx.x * 128, h = blockIdx.y;

    const __half* Qp = g_Q + (size_t)h * SEQ * EMB + (size_t)qb * EMB;
    const __half* Kp = g_K + (size_t)h * SEQ * EMB;
    const __half* Vp = g_V + (size_t)h * SEQ * EMB;

    const uint32_t qbase = sb + 3 * AT_BUF;
#pragma unroll
    for (int t = 0; t < 8; t++) {
        int idx = tid + t * 256;
        int r = idx >> 4, s = idx & 15;
        cpa(qbase + r * 272 + s * 16, Qp + r * EMB + s * 8);
    }
    CP_COMMIT();

    auto issue = [&](int kt) {
        uint32_t b = sb + (kt % 3) * AT_BUF;
        int kb = kt * 64;
#pragma unroll
        for (int t = 0; t < 4; t++) {
            int idx = tid + t * 256;
            int r = idx >> 4, s = idx & 15;
            uint32_t d = b + r * 272 + s * 16;
            const int go = (kb + r) * EMB + s * 8;
            cpa(d,         Kp + go);
            cpa(d + KT_SZ, Vp + go);
        }
        CP_COMMIT();
    };
    issue(0); issue(1);

    asm volatile("cp.async.wait_group 2;");   // Q arrived
    __syncthreads();

    uint32_t qah[8][4];
    const uint32_t qa_off = (uint32_t)((w * 16 + (lane & 15)) * 272 + (lane >> 4) * 16);
#pragma unroll
    for (int kk = 0; kk < 8; kk++)
        LDSM4(qah[kk], qbase + qa_off + kk * 32);

    float o[16][4];
#pragma unroll
    for (int j = 0; j < 16; j++)
#pragma unroll
        for (int p = 0; p < 4; p++) o[j][p] = 0.f;
    float mrow0 = -1e30f, mrow1 = -1e30f, lrow0 = 0.f, lrow1 = 0.f;

    const int g = lane >> 2, t4 = lane & 3;
    const uint32_t kb_row = (uint32_t)(((lane >> 4) << 3) + (lane & 7));
    const uint32_t kb_cadd = (uint32_t)(((lane >> 3) & 1) * 16);
    const uint32_t vb_row = (uint32_t)((((lane >> 3) & 1) * 8) + (lane & 7));
    const uint32_t vb_cadd = (uint32_t)((lane >> 4) * 16);

#pragma unroll 1
    for (int kt = 0; kt < 32; kt++) {
        if (kt < 31) asm volatile("cp.async.wait_group 1;");
        else         asm volatile("cp.async.wait_group 0;");
        __syncthreads();
        if (kt + 2 < 32) issue(kt + 2);
        const uint32_t kbuf = sb + (kt % 3) * AT_BUF;

        // ---- S = Q @ K^T  (64 mmas) ----
        float s[8][4];
#pragma unroll
        for (int j = 0; j < 8; j++)
#pragma unroll
            for (int p = 0; p < 4; p++) s[j][p] = 0.f;
#pragma unroll
        for (int kk = 0; kk < 8; kk++) {
#pragma unroll
            for (int np = 0; np < 4; np++) {
                uint32_t ba = kbuf + (np * 16 + kb_row) * 272 + kk * 32 + kb_cadd;
                uint32_t bh[4];
                LDSM4(bh, ba);
                mma16816(s[2 * np],     qah[kk], bh[0], bh[1]);
                mma16816(s[2 * np + 1], qah[kk], bh[2], bh[3]);
            }
        }

        // ---- online softmax ----
        float mx0 = -1e30f, mx1 = -1e30f;
#pragma unroll
        for (int j = 0; j < 8; j++) {
            mx0 = fmaxf(mx0, fmaxf(s[j][0], s[j][1]));
            mx1 = fmaxf(mx1, fmaxf(s[j][2], s[j][3]));
        }
        mx0 = fmaxf(mx0, __shfl_xor_sync(0xffffffffu, mx0, 1));
        mx0 = fmaxf(mx0, __shfl_xor_sync(0xffffffffu, mx0, 2));
        mx1 = fmaxf(mx1, __shfl_xor_sync(0xffffffffu, mx1, 1));
        mx1 = fmaxf(mx1, __shfl_xor_sync(0xffffffffu, mx1, 2));
        float mn0 = fmaxf(mrow0, mx0), mn1 = fmaxf(mrow1, mx1);
        float al0 = ex2f_(mrow0 - mn0), al1 = ex2f_(mrow1 - mn1);
        float rs0 = 0.f, rs1 = 0.f;
#pragma unroll
        for (int j = 0; j < 8; j++) {
            s[j][0] = ex2f_(s[j][0] - mn0);
            s[j][1] = ex2f_(s[j][1] - mn0);
            s[j][2] = ex2f_(s[j][2] - mn1);
            s[j][3] = ex2f_(s[j][3] - mn1);
            rs0 += s[j][0] + s[j][1];
            rs1 += s[j][2] + s[j][3];
        }
        rs0 += __shfl_xor_sync(0xffffffffu, rs0, 1);
        rs0 += __shfl_xor_sync(0xffffffffu, rs0, 2);
        rs1 += __shfl_xor_sync(0xffffffffu, rs1, 1);
        rs1 += __shfl_xor_sync(0xffffffffu, rs1, 2);
        lrow0 = lrow0 * al0 + rs0; mrow0 = mn0;
        lrow1 = lrow1 * al1 + rs1; mrow1 = mn1;
#pragma unroll
        for (int j = 0; j < 16; j++) {
            o[j][0] *= al0; o[j][1] *= al0; o[j][2] *= al1; o[j][3] *= al1;
        }

        // ---- O += P @ V  (P single fp16; 64 mmas) ----
        const uint32_t vbuf = kbuf + KT_SZ;
#pragma unroll
        for (int kk = 0; kk < 4; kk++) {
            uint32_t pah[4];
            pah[0] = pkh(__float2half_rn(s[2 * kk][0]),     __float2half_rn(s[2 * kk][1]));
            pah[1] = pkh(__float2half_rn(s[2 * kk][2]),     __float2half_rn(s[2 * kk][3]));
            pah[2] = pkh(__float2half_rn(s[2 * kk + 1][0]), __float2half_rn(s[2 * kk + 1][1]));
            pah[3] = pkh(__float2half_rn(s[2 * kk + 1][2]), __float2half_rn(s[2 * kk + 1][3]));
#pragma unroll
            for (int np = 0; np < 8; np++) {
                uint32_t va = vbuf + (kk * 16 + vb_row) * 272 + np * 32 + vb_cadd;
                uint32_t vh4[4];
                LDSM4T(vh4, va);
                mma16816(o[2 * np],     pah, vh4[0], vh4[1]);
                mma16816(o[2 * np + 1], pah, vh4[2], vh4[3]);
            }
        }
    }

    // ---- epilogue: normalize -> single fp16 Z ----
    const float rl0 = 1.0f / lrow0, rl1 = 1.0f / lrow1;
    const int r0 = qb + w * 16 + g, r1 = r0 + 8;
    __half* Z0 = g_Z + (size_t)r0 * HK + h * EMB;
    __half* Z1 = g_Z + (size_t)r1 * HK + h * EMB;
#pragma unroll
    for (int j = 0; j < 16; j++) {
        int col = 8 * j + 2 * t4;
        *(uint32_t*)&Z0[col] = pkh(__float2half_rn(o[j][0] * rl0), __float2half_rn(o[j][1] * rl0));
        *(uint32_t*)&Z1[col] = pkh(__float2half_rn(o[j][2] * rl1), __float2half_rn(o[j][3] * rl1));
    }
}

// =======================================================================
// gemm_proj_mma: split-K proj, 1-term fp16, 2-stage.
// =======================================================================
__global__ __launch_bounds__(256, 2)
void gemm_proj_mma()
{
    extern __shared__ char smem[];
    const uint32_t sb = smem_u32(smem);
    const int tid = threadIdx.x, w = tid >> 5, lane = tid & 31;
    const int row0 = blockIdx.x * 128;
    const int ks   = blockIdx.y;
    const int wr = w >> 1, wc = w & 1;

    const __half* zp = g_Z + (size_t)row0 * HK + ks * 256;
    const __half* pp = g_P + (size_t)ks * 256 * EMB;

    auto issue = [&](int kt) {
        uint32_t b = sb + (kt & 1) * QKV_BUF;
        int k0 = kt * 64;
#pragma unroll
        for (int t = 0; t < 4; t++) {
            int idx = tid + t * 256;
            int r = idx >> 3, s = idx & 7;
            cpa(b + r * 144 + s * 16, zp + r * HK + k0 + s * 8);
        }
#pragma unroll
        for (int t = 0; t < 4; t++) {
            int idx = tid + t * 256;
            int r = idx >> 4, s = idx & 15;
            cpa(b + XT_SZ + r * 272 + s * 16, pp + (k0 + r) * EMB + s * 8);
        }
        CP_COMMIT();
    };
    issue(0); issue(1);

    float c[2][8][4];
#pragma unroll
    for (int rt = 0; rt < 2; rt++)
#pragma unroll
        for (int j = 0; j < 8; j++)
#pragma unroll
            for (int p = 0; p < 4; p++) c[rt][j][p] = 0.f;

    const int g = lane >> 2, t4 = lane & 3;
    const uint32_t a_off = (uint32_t)((wr * 32 + (lane & 15)) * 144 + (lane >> 4) * 16);
    const uint32_t b_off = (uint32_t)(XT_SZ +
        (((lane >> 3) & 1) * 8 + (lane & 7)) * 272 + wc * 128 + (lane >> 4) * 16);

#pragma unroll 1
    for (int kt = 0; kt < 4; kt++) {
        if (kt < 3) asm volatile("cp.async.wait_group 1;");
        else        asm volatile("cp.async.wait_group 0;");
        __syncthreads();
        const uint32_t xb = sb + (kt & 1) * QKV_BUF;

#pragma unroll
        for (int kk = 0; kk < 4; kk++) {
            uint32_t ah[2][4];
#pragma unroll
            for (int rt = 0; rt < 2; rt++)
                LDSM4(ah[rt], xb + a_off + rt * 16 * 144 + kk * 32);
#pragma unroll
            for (int np = 0; np < 4; np++) {
                uint32_t ba = xb + b_off + kk * 16 * 272 + np * 32;
                uint32_t bh[4];
                LDSM4T(bh, ba);
#pragma unroll
                for (int rt = 0; rt < 2; rt++) {
                    mma16816(c[rt][2 * np],     ah[rt], bh[0], bh[1]);
                    mma16816(c[rt][2 * np + 1], ah[rt], bh[2], bh[3]);
                }
            }
        }
        __syncthreads();
        if (kt + 2 < 4) issue(kt + 2);
    }

    float* Pp = g_Pp + (size_t)blockIdx.y * SEQ * EMB;
#pragma unroll
    for (int rt = 0; rt < 2; rt++) {
        const int r0 = row0 + wr * 32 + rt * 16 + g, r1 = r0 + 8;
#pragma unroll
        for (int j = 0; j < 8; j++) {
            int col = wc * 64 + 8 * j + 2 * t4;
            *(float2*)&Pp[r0 * EMB + col] = make_float2(c[rt][j][0], c[rt][j][1]);
            *(float2*)&Pp[r1 * EMB + col] = make_float2(c[rt][j][2], c[rt][j][3]);
        }
    }
}

__global__ __launch_bounds__(256)
void proj_reduce(float* __restrict__ out)
{
    int gid = blockIdx.x * 256 + threadIdx.x;
    const float4* p = (const float4*)g_Pp;
    const int STR = SEQ * EMB / 4;
    float4 s = p[gid];
#pragma unroll
    for (int z = 1; z < NSPLIT; z++) {
        float4 t = p[z * STR + gid];
        s.x += t.x; s.y += t.y; s.z += t.z; s.w += t.w;
    }
    ((float4*)out)[gid] = s;
}

// =======================================================================
extern "C" void kernel_launch(void* const* d_in, const int* in_sizes, int n_in,
                              void* d_out, int out_size)
{
    (void)in_sizes; (void)n_in; (void)out_size;
    const float* x    = (const float*)d_in[0];
    const float* Wq   = (const float*)d_in[1];
    const float* bq   = (const float*)d_in[2];
    const float* Wk   = (const float*)d_in[3];
    const float* bk   = (const float*)d_in[4];
    const float* Wv   = (const float*)d_in[5];
    const float* bv   = (const float*)d_in[6];
    const float* proj = (const float*)d_in[7];
    float* out = (float*)d_out;

    cudaFuncSetAttribute(gemm_qkv_mma,  cudaFuncAttributeMaxDynamicSharedMemorySize, QKV_SMEM3);
    cudaFuncSetAttribute(attn_mma,      cudaFuncAttributeMaxDynamicSharedMemorySize, ATT_SMEM);
    cudaFuncSetAttribute(gemm_proj_mma, cudaFuncAttributeMaxDynamicSharedMemorySize, PRJ_SMEM);

    conv_x<<<SEQ * WORD / 1024, 256>>>(x);
    conv_w<<<48 * WORD * EMB / 1024, 256>>>(Wq, Wk, Wv);
    conv_p<<<HK * EMB / 1024, 256>>>(proj);

    gemm_qkv_mma<<<dim3(SEQ / 128, 48), 256, QKV_SMEM3>>>(bq, bk, bv);

    attn_mma<<<dim3(SEQ / 128, NH), 256, ATT_SMEM>>>();

    gemm_proj_mma<<<dim3(SEQ / 128, NSPLIT), 256, PRJ_SMEM>>>();
    proj_reduce<<<SEQ * EMB / 1024, 256>>>(out);
}